// round 2
// baseline (speedup 1.0000x reference)
#include <cuda_runtime.h>
#include <cuda_bf16.h>

#define NKER 25
#define HP   8        // padded inner dim (6 feats + basis-sum + pad)
#define HROW 200      // NKER * HP floats per node
#define HW   150      // logical 25*6
#define JD   156      // 150 + 6 (H rows + x rows)
#define CD   78       // 75 Z cols + 3 root cols
#define CP   80       // padded smem pitch
#define NMAX 50000
#define EMAX 1600000

// scratch (no cudaMalloc allowed)
__device__ float  g_H[NMAX * HROW];     // 40 MB, [n][k][8]: 6 feats, slot6=Σbasis(deg), slot7 pad
__device__ float  g_inv[NMAX];
__device__ float4 g_Z4[NMAX * NKER];    // 20 MB, (z0,z1,z2,pad) per (n,kk)
__device__ float4 g_A4[NMAX];           // edge-2 accumulator
__device__ float  g_M[JD * CD];         // fused weight matrix

// ---------------------------------------------------------------------------
__global__ void k_zero(int N) {
    int i = blockIdx.x * blockDim.x + threadIdx.x;
    int stride = gridDim.x * blockDim.x;
    float4 z4 = make_float4(0.f, 0.f, 0.f, 0.f);
    float4* H4 = reinterpret_cast<float4*>(g_H);
    int nH4 = N * (HROW / 4);
    for (int t = i; t < nH4; t += stride) H4[t] = z4;
    for (int t = i; t < N; t += stride) g_A4[t] = z4;
}

// degree-1 open B-spline, K=5: 4 corners
__device__ __forceinline__ void spline4(float p0, float p1, float* b, int* id) {
    float v0 = p0 * 4.0f, v1 = p1 * 4.0f;
    float fl0 = floorf(v0), fl1 = floorf(v1);
    int i0 = (int)fl0, i1 = (int)fl1;
    i0 = min(max(i0, 0), 3);
    i1 = min(max(i1, 0), 3);
    float f0 = v0 - fl0, f1 = v1 - fl1;
    float g0 = 1.0f - f0, g1 = 1.0f - f1;
    b[0] = g0 * g1; b[1] = f0 * g1; b[2] = g0 * f1; b[3] = f0 * f1;
    int base = i0 + 5 * i1;
    id[0] = base; id[1] = base + 1; id[2] = base + 5; id[3] = base + 6;
}

// ---------------------------------------------------------------------------
// Edge pass 1: H[dst, idx_s, 0:6] += basis_s * x[src, :]; slot6 += basis_s
// (Σ_s basis_s == 1, so Σ_k H[n][k][6] == deg[n] — degree comes for free)
__global__ void k_edge1(const int* __restrict__ ei, const float* __restrict__ ps,
                        const float* __restrict__ x, int E) {
    int e = blockIdx.x * blockDim.x + threadIdx.x;
    if (e >= E) return;
    int dst = ei[e];
    int src = ei[E + e];
    float2 p = reinterpret_cast<const float2*>(ps)[e];
    float b[4]; int id[4];
    spline4(p.x, p.y, b, id);
    const float2* x2 = reinterpret_cast<const float2*>(x) + src * 3;
    float2 xa = x2[0], xb = x2[1], xc = x2[2];
    float4* Hd = reinterpret_cast<float4*>(g_H + (size_t)dst * HROW);
#pragma unroll
    for (int s = 0; s < 4; s++) {
        float bs = b[s];
        float4* hp = Hd + id[s] * 2;
        atomicAdd(hp,     make_float4(bs * xa.x, bs * xa.y, bs * xb.x, bs * xb.y));
        atomicAdd(hp + 1, make_float4(bs * xc.x, bs * xc.y, bs, 0.f));
    }
}

// ---------------------------------------------------------------------------
// Build fused M (156 x 78):
//   rows j<150: Wf[j=k*6+i, :] = weight[k,i,:1024] ; rows 150..155: root_weight
//   cols c<75:  Wc[:, c=3kk+oo] = weight1[kk,:,oo] ; cols 75..77: root_weight1
__global__ void k_buildM(const float* __restrict__ w, const float* __restrict__ rw,
                         const float* __restrict__ w1, const float* __restrict__ rw1) {
    __shared__ float sA[1024];
    int j = blockIdx.x;
    const float* Arow = (j < HW) ? (w + (j / 6) * 6144 + (j % 6) * 1024)
                                 : (rw + (j - HW) * 1024);
    for (int i = threadIdx.x; i < 1024; i += blockDim.x) sA[i] = Arow[i];
    __syncthreads();
    for (int c = threadIdx.x; c < CD; c += blockDim.x) {
        const float* Bp = (c < 75) ? (w1 + (c / 3) * 3072 + (c % 3)) : (rw1 + (c - 75));
        float acc = 0.f;
#pragma unroll 8
        for (int i = 0; i < 1024; i++) acc = fmaf(sA[i], __ldg(Bp + i * 3), acc);
        g_M[j * CD + c] = acc;
    }
}

// ---------------------------------------------------------------------------
// Z GEMM: per node n, Zext[n, 0:78] = (Hrow(150)/deg | x(6)) @ M(156x78)
// cols 0..74 -> g_Z4 packed float4 per (n,kk) ; cols 75..77 -> d_out (root term)
// block: 64 nodes, threads (13,16): each thread 4 nodes x 2 kk-groups (6 cols)
__global__ void k_zgemm(const float* __restrict__ x, float* __restrict__ dout, int N) {
    extern __shared__ float sm[];
    float* sM = sm;                 // JD*CP = 12480 floats
    float* sH = sm + JD * CP;       // 64*157 = 10048 floats
    __shared__ float sInv[64];
    int tx = threadIdx.x, ty = threadIdx.y;
    int tid = ty * 13 + tx;
    int n0 = blockIdx.x * 64;

    if (tid < 64) {
        int n = n0 + tid;
        float d = 0.f;
        if (n < N) {
            const float* hn = g_H + (size_t)n * HROW + 6;
#pragma unroll
            for (int k = 0; k < NKER; k++) d += hn[k * HP];
        }
        float inv = 1.0f / fmaxf(d, 1.0f);
        sInv[tid] = inv;
        if (n < N) g_inv[n] = inv;
    }
    __syncthreads();

    for (int idx = tid; idx < JD * CD; idx += 208) {
        int j = idx / CD, c = idx - j * CD;
        sM[j * CP + c] = g_M[idx];
    }
    for (int idx = tid; idx < 64 * JD; idx += 208) {
        int r = idx / JD, j = idx - r * JD;
        int n = n0 + r;
        float v = 0.f;
        if (n < N) {
            if (j < HW) {
                int k = j / 6, i = j - k * 6;
                v = g_H[(size_t)n * HROW + k * HP + i] * sInv[r];
            } else {
                v = x[n * 6 + (j - HW)];
            }
        }
        sH[r * 157 + j] = v;
    }
    __syncthreads();

    float acc[4][6];
#pragma unroll
    for (int r = 0; r < 4; r++)
#pragma unroll
        for (int u = 0; u < 6; u++) acc[r][u] = 0.f;

    int c0 = 3 * tx;
    int c1 = 3 * (tx + 13);
    int rbase = ty * 4;

#pragma unroll 2
    for (int j = 0; j < JD; j++) {
        float a0 = sH[(rbase + 0) * 157 + j];
        float a1 = sH[(rbase + 1) * 157 + j];
        float a2 = sH[(rbase + 2) * 157 + j];
        float a3 = sH[(rbase + 3) * 157 + j];
        const float* mr = sM + j * CP;
        float b0 = mr[c0], b1 = mr[c0 + 1], b2 = mr[c0 + 2];
        float b3 = mr[c1], b4 = mr[c1 + 1], b5 = mr[c1 + 2];
        acc[0][0] = fmaf(a0, b0, acc[0][0]); acc[0][1] = fmaf(a0, b1, acc[0][1]); acc[0][2] = fmaf(a0, b2, acc[0][2]);
        acc[0][3] = fmaf(a0, b3, acc[0][3]); acc[0][4] = fmaf(a0, b4, acc[0][4]); acc[0][5] = fmaf(a0, b5, acc[0][5]);
        acc[1][0] = fmaf(a1, b0, acc[1][0]); acc[1][1] = fmaf(a1, b1, acc[1][1]); acc[1][2] = fmaf(a1, b2, acc[1][2]);
        acc[1][3] = fmaf(a1, b3, acc[1][3]); acc[1][4] = fmaf(a1, b4, acc[1][4]); acc[1][5] = fmaf(a1, b5, acc[1][5]);
        acc[2][0] = fmaf(a2, b0, acc[2][0]); acc[2][1] = fmaf(a2, b1, acc[2][1]); acc[2][2] = fmaf(a2, b2, acc[2][2]);
        acc[2][3] = fmaf(a2, b3, acc[2][3]); acc[2][4] = fmaf(a2, b4, acc[2][4]); acc[2][5] = fmaf(a2, b5, acc[2][5]);
        acc[3][0] = fmaf(a3, b0, acc[3][0]); acc[3][1] = fmaf(a3, b1, acc[3][1]); acc[3][2] = fmaf(a3, b2, acc[3][2]);
        acc[3][3] = fmaf(a3, b3, acc[3][3]); acc[3][4] = fmaf(a3, b4, acc[3][4]); acc[3][5] = fmaf(a3, b5, acc[3][5]);
    }

#pragma unroll
    for (int r = 0; r < 4; r++) {
        int n = n0 + rbase + r;
        if (n >= N) continue;
        g_Z4[(size_t)n * NKER + tx] = make_float4(acc[r][0], acc[r][1], acc[r][2], 0.f);
        if (tx == 12) {
            dout[n * 3 + 0] = acc[r][3];
            dout[n * 3 + 1] = acc[r][4];
            dout[n * 3 + 2] = acc[r][5];
        } else {
            g_Z4[(size_t)n * NKER + tx + 13] = make_float4(acc[r][3], acc[r][4], acc[r][5], 0.f);
        }
    }
}

// ---------------------------------------------------------------------------
// Edge pass 2: A4[dst] += sum_s basis1_s * Z[src, idx_s, :]  (one float4 atomic)
__global__ void k_edge2(const int* __restrict__ ei, const float* __restrict__ ps,
                        int E) {
    int e = blockIdx.x * blockDim.x + threadIdx.x;
    if (e >= E) return;
    int dst = ei[e];
    int src = ei[E + e];
    float2 p = reinterpret_cast<const float2*>(ps)[e];
    float b[4]; int id[4];
    spline4(p.x, p.y, b, id);
    const float4* Z = g_Z4 + (size_t)src * NKER;
    float a0 = 0.f, a1 = 0.f, a2 = 0.f;
#pragma unroll
    for (int s = 0; s < 4; s++) {
        float4 z = __ldg(Z + id[s]);
        a0 = fmaf(b[s], z.x, a0);
        a1 = fmaf(b[s], z.y, a1);
        a2 = fmaf(b[s], z.z, a2);
    }
    atomicAdd(g_A4 + dst, make_float4(a0, a1, a2, 0.f));
}

// ---------------------------------------------------------------------------
// Final: out[n] = root_term (already in dout) + inv[n] * A4[n]
__global__ void k_final(float* __restrict__ dout, int N) {
    int n = blockIdx.x * blockDim.x + threadIdx.x;
    if (n >= N) return;
    float4 a = g_A4[n];
    float inv = g_inv[n];
    dout[n * 3 + 0] += a.x * inv;
    dout[n * 3 + 1] += a.y * inv;
    dout[n * 3 + 2] += a.z * inv;
}

// ---------------------------------------------------------------------------
extern "C" void kernel_launch(void* const* d_in, const int* in_sizes, int n_in,
                              void* d_out, int out_size) {
    const float* x   = (const float*)d_in[0];
    const int*   ei  = (const int*)d_in[1];
    const float* ps  = (const float*)d_in[2];
    const float* ps1 = (const float*)d_in[3];
    const float* w   = (const float*)d_in[4];
    const float* rw  = (const float*)d_in[5];
    const float* w1  = (const float*)d_in[6];
    const float* rw1 = (const float*)d_in[7];
    float* dout = (float*)d_out;

    int N = in_sizes[0] / 6;
    int E = in_sizes[2] / 2;
    if (N > NMAX) N = NMAX;
    if (E > EMAX) E = EMAX;

    k_zero<<<2048, 256>>>(N);
    k_edge1<<<(E + 255) / 256, 256>>>(ei, ps, x, E);
    k_buildM<<<JD, 128>>>(w, rw, w1, rw1);

    size_t smemC = (size_t)(JD * CP + 64 * 157) * sizeof(float);   // 90112 B
    cudaFuncSetAttribute(k_zgemm, cudaFuncAttributeMaxDynamicSharedMemorySize, (int)smemC);
    k_zgemm<<<(N + 63) / 64, dim3(13, 16), smemC>>>(x, dout, N);

    k_edge2<<<(E + 255) / 256, 256>>>(ei, ps1, E);
    k_final<<<(N + 255) / 256, 256>>>(dout, N);
}

// round 3
// speedup vs baseline: 1.0729x; 1.0729x over previous
#include <cuda_runtime.h>
#include <cuda_bf16.h>

#define NKER 25
#define HP   8        // padded inner dim (6 feats + basis-sum + pad)
#define HROW 200      // NKER * HP floats per node
#define HW   150      // logical 25*6
#define JD   156      // 150 + 6 (H rows + x rows)
#define CD   78       // 75 Z cols + 3 root cols
#define NMAX 50000
#define EMAX 1600000

// zgemm tiling
#define BN   128      // nodes per block
#define PH   132      // sHt pitch (floats): 16B-aligned, bank-staggered
#define PM   104      // sM pitch: 26 groups * 4

// scratch (no cudaMalloc allowed)
__device__ float  g_H[NMAX * HROW];     // 40 MB, [n][k][8]: 6 feats, slot6=Σbasis(deg), slot7 pad
__device__ float  g_inv[NMAX];
__device__ float4 g_Z4[NMAX * NKER];    // 20 MB, (z0,z1,z2,pad) per (n,kk)
__device__ float4 g_A4[NMAX];           // edge-2 accumulator
__device__ float  g_M[JD * CD];         // fused weight matrix

// ---------------------------------------------------------------------------
__global__ void k_zero(int N) {
    int i = blockIdx.x * blockDim.x + threadIdx.x;
    int stride = gridDim.x * blockDim.x;
    float4 z4 = make_float4(0.f, 0.f, 0.f, 0.f);
    float4* H4 = reinterpret_cast<float4*>(g_H);
    int nH4 = N * (HROW / 4);
    for (int t = i; t < nH4; t += stride) H4[t] = z4;
    for (int t = i; t < N; t += stride) g_A4[t] = z4;
}

// degree-1 open B-spline, K=5: 4 corners
__device__ __forceinline__ void spline4(float p0, float p1, float* b, int* id) {
    float v0 = p0 * 4.0f, v1 = p1 * 4.0f;
    float fl0 = floorf(v0), fl1 = floorf(v1);
    int i0 = (int)fl0, i1 = (int)fl1;
    i0 = min(max(i0, 0), 3);
    i1 = min(max(i1, 0), 3);
    float f0 = v0 - fl0, f1 = v1 - fl1;
    float g0 = 1.0f - f0, g1 = 1.0f - f1;
    b[0] = g0 * g1; b[1] = f0 * g1; b[2] = g0 * f1; b[3] = f0 * f1;
    int base = i0 + 5 * i1;
    id[0] = base; id[1] = base + 1; id[2] = base + 5; id[3] = base + 6;
}

// ---------------------------------------------------------------------------
// Edge pass 1: H[dst, idx_s, 0:6] += basis_s * x[src, :]; slot6 += basis_s
__global__ void k_edge1(const int* __restrict__ ei, const float* __restrict__ ps,
                        const float* __restrict__ x, int E) {
    int e = blockIdx.x * blockDim.x + threadIdx.x;
    if (e >= E) return;
    int dst = ei[e];
    int src = ei[E + e];
    float2 p = reinterpret_cast<const float2*>(ps)[e];
    float b[4]; int id[4];
    spline4(p.x, p.y, b, id);
    const float2* x2 = reinterpret_cast<const float2*>(x) + src * 3;
    float2 xa = x2[0], xb = x2[1], xc = x2[2];
    float4* Hd = reinterpret_cast<float4*>(g_H + (size_t)dst * HROW);
#pragma unroll
    for (int s = 0; s < 4; s++) {
        float bs = b[s];
        float4* hp = Hd + id[s] * 2;
        atomicAdd(hp,     make_float4(bs * xa.x, bs * xa.y, bs * xb.x, bs * xb.y));
        atomicAdd(hp + 1, make_float4(bs * xc.x, bs * xc.y, bs, 0.f));
    }
}

// ---------------------------------------------------------------------------
// Build fused M (156 x 78)
__global__ void k_buildM(const float* __restrict__ w, const float* __restrict__ rw,
                         const float* __restrict__ w1, const float* __restrict__ rw1) {
    __shared__ float sA[1024];
    int j = blockIdx.x;
    const float* Arow = (j < HW) ? (w + (j / 6) * 6144 + (j % 6) * 1024)
                                 : (rw + (j - HW) * 1024);
    for (int i = threadIdx.x; i < 1024; i += blockDim.x) sA[i] = Arow[i];
    __syncthreads();
    for (int c = threadIdx.x; c < CD; c += blockDim.x) {
        const float* Bp = (c < 75) ? (w1 + (c / 3) * 3072 + (c % 3)) : (rw1 + (c - 75));
        float acc = 0.f;
#pragma unroll 8
        for (int i = 0; i < 1024; i++) acc = fmaf(sA[i], __ldg(Bp + i * 3), acc);
        g_M[j * CD + c] = acc;
    }
}

// ---------------------------------------------------------------------------
// Z GEMM: Zext[n, 0:78] = (Hrow(150)/deg | x(6)) @ M(156x78)
// Block: 128 nodes, threads (13,16). Thread = 8 nodes x 6 cols (two 3-col groups).
// Per j: 2x LDS.128 a-values + 2x LDS.128 b-values -> 48 FMA.
__global__ void __launch_bounds__(208)
k_zgemm(const float* __restrict__ x, float* __restrict__ dout, int N) {
    extern __shared__ float sm[];
    float* sM  = sm;             // JD*PM = 16224 floats
    float* sHt = sm + JD * PM;   // JD*PH = 20592 floats  [j][node]
    __shared__ float sInv[BN];
    int tx = threadIdx.x, ty = threadIdx.y;
    int tid = ty * 13 + tx;
    int n0 = blockIdx.x * BN;

    // per-node inverse degree from slot6 sums
    if (tid < BN) {
        int n = n0 + tid;
        float d = 0.f;
        if (n < N) {
            const float* hn = g_H + (size_t)n * HROW + 6;
#pragma unroll
            for (int k = 0; k < NKER; k++) d += hn[k * HP];
        }
        float inv = 1.0f / fmaxf(d, 1.0f);
        sInv[tid] = inv;
        if (n < N) g_inv[n] = inv;
    }
    __syncthreads();

    // M -> sM, groups of 3 padded to 4 (pad = 0)
    for (int idx = tid; idx < JD * CD; idx += 208) {
        int j = idx / CD, c = idx - j * CD;
        sM[j * PM + 4 * (c / 3) + (c - 3 * (c / 3))] = g_M[idx];
    }
    for (int idx = tid; idx < JD * 26; idx += 208) {
        int j = idx / 26, g = idx - j * 26;
        sM[j * PM + 4 * g + 3] = 0.f;
    }

    // H -> sHt transposed: sHt[j*PH + r] = H[n0+r][j] * inv ; x rows unscaled
    for (int idx = tid; idx < BN * 50; idx += 208) {
        int r = idx / 50, f = idx - r * 50;
        int n = n0 + r;
        float4 h = make_float4(0.f, 0.f, 0.f, 0.f);
        if (n < N)
            h = reinterpret_cast<const float4*>(g_H + (size_t)n * HROW)[f];
        float inv = sInv[r];
        int k = f >> 1;
        if ((f & 1) == 0) {
            int j = k * 6;
            sHt[(j + 0) * PH + r] = h.x * inv;
            sHt[(j + 1) * PH + r] = h.y * inv;
            sHt[(j + 2) * PH + r] = h.z * inv;
            sHt[(j + 3) * PH + r] = h.w * inv;
        } else {
            int j = k * 6 + 4;
            sHt[(j + 0) * PH + r] = h.x * inv;
            sHt[(j + 1) * PH + r] = h.y * inv;
            // h.z = basis-sum, h.w = pad: not part of A
        }
    }
    for (int idx = tid; idx < BN * 6; idx += 208) {
        int r = idx / 6, i = idx - r * 6;
        int n = n0 + r;
        sHt[(HW + i) * PH + r] = (n < N) ? x[n * 6 + i] : 0.f;
    }
    __syncthreads();

    float acc[8][6];
#pragma unroll
    for (int rr = 0; rr < 8; rr++)
#pragma unroll
        for (int u = 0; u < 6; u++) acc[rr][u] = 0.f;

    int r0 = ty * 8;
    int bcol = 8 * tx;

#pragma unroll 2
    for (int j = 0; j < JD; j++) {
        const float* hj = sHt + j * PH + r0;
        float4 a0 = *reinterpret_cast<const float4*>(hj);
        float4 a1 = *reinterpret_cast<const float4*>(hj + 4);
        const float* mj = sM + j * PM + bcol;
        float4 b0 = *reinterpret_cast<const float4*>(mj);
        float4 b1 = *reinterpret_cast<const float4*>(mj + 4);
        float av[8] = {a0.x, a0.y, a0.z, a0.w, a1.x, a1.y, a1.z, a1.w};
#pragma unroll
        for (int rr = 0; rr < 8; rr++) {
            float a = av[rr];
            acc[rr][0] = fmaf(a, b0.x, acc[rr][0]);
            acc[rr][1] = fmaf(a, b0.y, acc[rr][1]);
            acc[rr][2] = fmaf(a, b0.z, acc[rr][2]);
            acc[rr][3] = fmaf(a, b1.x, acc[rr][3]);
            acc[rr][4] = fmaf(a, b1.y, acc[rr][4]);
            acc[rr][5] = fmaf(a, b1.z, acc[rr][5]);
        }
    }

#pragma unroll
    for (int rr = 0; rr < 8; rr++) {
        int n = n0 + r0 + rr;
        if (n >= N) continue;
        g_Z4[(size_t)n * NKER + 2 * tx] = make_float4(acc[rr][0], acc[rr][1], acc[rr][2], 0.f);
        if (tx == 12) {
            dout[n * 3 + 0] = acc[rr][3];
            dout[n * 3 + 1] = acc[rr][4];
            dout[n * 3 + 2] = acc[rr][5];
        } else {
            g_Z4[(size_t)n * NKER + 2 * tx + 1] = make_float4(acc[rr][3], acc[rr][4], acc[rr][5], 0.f);
        }
    }
}

// ---------------------------------------------------------------------------
// Edge pass 2: A4[dst] += sum_s basis1_s * Z[src, idx_s, :]  (one float4 atomic)
__global__ void k_edge2(const int* __restrict__ ei, const float* __restrict__ ps,
                        int E) {
    int e = blockIdx.x * blockDim.x + threadIdx.x;
    if (e >= E) return;
    int dst = ei[e];
    int src = ei[E + e];
    float2 p = reinterpret_cast<const float2*>(ps)[e];
    float b[4]; int id[4];
    spline4(p.x, p.y, b, id);
    const float4* Z = g_Z4 + (size_t)src * NKER;
    float a0 = 0.f, a1 = 0.f, a2 = 0.f;
#pragma unroll
    for (int s = 0; s < 4; s++) {
        float4 z = __ldg(Z + id[s]);
        a0 = fmaf(b[s], z.x, a0);
        a1 = fmaf(b[s], z.y, a1);
        a2 = fmaf(b[s], z.z, a2);
    }
    atomicAdd(g_A4 + dst, make_float4(a0, a1, a2, 0.f));
}

// ---------------------------------------------------------------------------
// Final: out[n] = root_term (already in dout) + inv[n] * A4[n]
__global__ void k_final(float* __restrict__ dout, int N) {
    int n = blockIdx.x * blockDim.x + threadIdx.x;
    if (n >= N) return;
    float4 a = g_A4[n];
    float inv = g_inv[n];
    dout[n * 3 + 0] += a.x * inv;
    dout[n * 3 + 1] += a.y * inv;
    dout[n * 3 + 2] += a.z * inv;
}

// ---------------------------------------------------------------------------
extern "C" void kernel_launch(void* const* d_in, const int* in_sizes, int n_in,
                              void* d_out, int out_size) {
    const float* x   = (const float*)d_in[0];
    const int*   ei  = (const int*)d_in[1];
    const float* ps  = (const float*)d_in[2];
    const float* ps1 = (const float*)d_in[3];
    const float* w   = (const float*)d_in[4];
    const float* rw  = (const float*)d_in[5];
    const float* w1  = (const float*)d_in[6];
    const float* rw1 = (const float*)d_in[7];
    float* dout = (float*)d_out;

    int N = in_sizes[0] / 6;
    int E = in_sizes[2] / 2;
    if (N > NMAX) N = NMAX;
    if (E > EMAX) E = EMAX;

    k_zero<<<2048, 256>>>(N);
    k_edge1<<<(E + 255) / 256, 256>>>(ei, ps, x, E);
    k_buildM<<<JD, 128>>>(w, rw, w1, rw1);

    size_t smemC = (size_t)(JD * PM + JD * PH) * sizeof(float);   // 147264 B
    cudaFuncSetAttribute(k_zgemm, cudaFuncAttributeMaxDynamicSharedMemorySize, (int)smemC);
    k_zgemm<<<(N + BN - 1) / BN, dim3(13, 16), smemC>>>(x, dout, N);

    k_edge2<<<(E + 255) / 256, 256>>>(ei, ps1, E);
    k_final<<<(N + 255) / 256, 256>>>(dout, N);
}

// round 4
// speedup vs baseline: 1.2558x; 1.1706x over previous
#include <cuda_runtime.h>
#include <cuda_bf16.h>

#define NKER 25
#define HP   8        // padded inner dim (6 feats + basis-sum + pad)
#define HROW 200      // NKER * HP floats per node
#define HW   150      // logical 25*6
#define JD   156      // 150 + 6 (H rows + x rows)
#define CD   78       // 75 Z cols + 3 root cols
#define MP   80       // sM pitch (floats), cols 78,79 zero
#define NMAX 50000
#define EMAX 1600000

// scratch (no cudaMalloc allowed)
__device__ float  g_H[NMAX * HROW];     // 40 MB, [n][k][8]: 6 feats, slot6=Σbasis(deg), slot7 pad
__device__ float  g_inv[NMAX];
__device__ float4 g_Z4[NMAX * NKER];    // 20 MB, (z0,z1,z2,pad) per (n,kk)
__device__ float4 g_A4[NMAX];           // edge-2 accumulator
__device__ float  g_M[JD * CD];         // fused weight matrix

// ---------------------------------------------------------------------------
__global__ void k_zero(int N) {
    int i = blockIdx.x * blockDim.x + threadIdx.x;
    int stride = gridDim.x * blockDim.x;
    float4 z4 = make_float4(0.f, 0.f, 0.f, 0.f);
    float4* H4 = reinterpret_cast<float4*>(g_H);
    int nH4 = N * (HROW / 4);
    for (int t = i; t < nH4; t += stride) H4[t] = z4;
    for (int t = i; t < N; t += stride) g_A4[t] = z4;
}

// degree-1 open B-spline, K=5: 4 corners
__device__ __forceinline__ void spline4(float p0, float p1, float* b, int* id) {
    float v0 = p0 * 4.0f, v1 = p1 * 4.0f;
    float fl0 = floorf(v0), fl1 = floorf(v1);
    int i0 = (int)fl0, i1 = (int)fl1;
    i0 = min(max(i0, 0), 3);
    i1 = min(max(i1, 0), 3);
    float f0 = v0 - fl0, f1 = v1 - fl1;
    float g0 = 1.0f - f0, g1 = 1.0f - f1;
    b[0] = g0 * g1; b[1] = f0 * g1; b[2] = g0 * f1; b[3] = f0 * f1;
    int base = i0 + 5 * i1;
    id[0] = base; id[1] = base + 1; id[2] = base + 5; id[3] = base + 6;
}

// ---------------------------------------------------------------------------
// Edge pass 1: H[dst, idx_s, 0:6] += basis_s * x[src, :]; slot6 += basis_s
__global__ void k_edge1(const int* __restrict__ ei, const float* __restrict__ ps,
                        const float* __restrict__ x, int E) {
    int e = blockIdx.x * blockDim.x + threadIdx.x;
    if (e >= E) return;
    int dst = ei[e];
    int src = ei[E + e];
    float2 p = reinterpret_cast<const float2*>(ps)[e];
    float b[4]; int id[4];
    spline4(p.x, p.y, b, id);
    const float2* x2 = reinterpret_cast<const float2*>(x) + src * 3;
    float2 xa = x2[0], xb = x2[1], xc = x2[2];
    float4* Hd = reinterpret_cast<float4*>(g_H + (size_t)dst * HROW);
#pragma unroll
    for (int s = 0; s < 4; s++) {
        float bs = b[s];
        float4* hp = Hd + id[s] * 2;
        atomicAdd(hp,     make_float4(bs * xa.x, bs * xa.y, bs * xb.x, bs * xb.y));
        atomicAdd(hp + 1, make_float4(bs * xc.x, bs * xc.y, bs, 0.f));
    }
}

// ---------------------------------------------------------------------------
// Build fused M (156 x 78). Block j; 4 i-slices per col, smem reduce.
__global__ void k_buildM(const float* __restrict__ w, const float* __restrict__ rw,
                         const float* __restrict__ w1, const float* __restrict__ rw1) {
    __shared__ float sA[1024];
    __shared__ float red[CD][4];
    int j = blockIdx.x;
    int tid = threadIdx.x;
    const float* Arow = (j < HW) ? (w + (j / 6) * 6144 + (j % 6) * 1024)
                                 : (rw + (j - HW) * 1024);
    for (int i = tid; i < 1024; i += blockDim.x) sA[i] = Arow[i];
    __syncthreads();
    int c = tid >> 2, sl = tid & 3;
    if (c < CD) {
        const float* Bp = (c < 75) ? (w1 + (c / 3) * 3072 + (c % 3)) : (rw1 + (c - 75));
        float acc = 0.f;
        int i0 = sl * 256;
#pragma unroll 8
        for (int i = i0; i < i0 + 256; i++) acc = fmaf(sA[i], __ldg(Bp + i * 3), acc);
        red[c][sl] = acc;
    }
    __syncthreads();
    if (tid < CD)
        g_M[j * CD + tid] = (red[tid][0] + red[tid][1]) + (red[tid][2] + red[tid][3]);
}

// ---------------------------------------------------------------------------
// Z GEMM: one thread = one node; acc over all 78 cols in registers.
// A streams from g_H (LDG.128, L2-hot); B broadcast from sM (LDS.128).
__global__ void __launch_bounds__(128, 4)
k_zgemm(const float* __restrict__ x, float* __restrict__ dout, int N) {
    extern __shared__ float sM[];   // JD * MP = 12480 floats = 49920 B
    int tid = threadIdx.x;
    // cooperative load of M (cols 78,79 zeroed)
    for (int idx = tid; idx < JD * MP; idx += 128) {
        int j = idx / MP, c = idx - j * MP;
        sM[idx] = (c < CD) ? g_M[j * CD + c] : 0.f;
    }
    __syncthreads();

    int n = blockIdx.x * 128 + tid;
    if (n >= N) return;

    float acc[80];
#pragma unroll
    for (int c = 0; c < 80; c++) acc[c] = 0.f;

    const float4* H4 = reinterpret_cast<const float4*>(g_H + (size_t)n * HROW);
    float d = 0.f;

    for (int k = 0; k < NKER; k++) {
        float4 h0 = __ldg(H4 + 2 * k);
        float4 h1 = __ldg(H4 + 2 * k + 1);
        d += h1.z;
        float av[6] = {h0.x, h0.y, h0.z, h0.w, h1.x, h1.y};
#pragma unroll
        for (int i = 0; i < 6; i++) {
            float a = av[i];
            const float4* m4 = reinterpret_cast<const float4*>(sM + (k * 6 + i) * MP);
#pragma unroll
            for (int g = 0; g < 20; g++) {
                float4 b = m4[g];
                acc[4 * g + 0] = fmaf(a, b.x, acc[4 * g + 0]);
                acc[4 * g + 1] = fmaf(a, b.y, acc[4 * g + 1]);
                acc[4 * g + 2] = fmaf(a, b.z, acc[4 * g + 2]);
                acc[4 * g + 3] = fmaf(a, b.w, acc[4 * g + 3]);
            }
        }
    }

    float inv = 1.0f / fmaxf(d, 1.0f);
    g_inv[n] = inv;
#pragma unroll
    for (int c = 0; c < 80; c++) acc[c] *= inv;

    // x part (rows 150..155 of M), unscaled
    const float2* x2 = reinterpret_cast<const float2*>(x) + n * 3;
    float2 xa = __ldg(x2), xb = __ldg(x2 + 1), xc = __ldg(x2 + 2);
    float xv[6] = {xa.x, xa.y, xb.x, xb.y, xc.x, xc.y};
#pragma unroll
    for (int i = 0; i < 6; i++) {
        float a = xv[i];
        const float4* m4 = reinterpret_cast<const float4*>(sM + (HW + i) * MP);
#pragma unroll
        for (int g = 0; g < 20; g++) {
            float4 b = m4[g];
            acc[4 * g + 0] = fmaf(a, b.x, acc[4 * g + 0]);
            acc[4 * g + 1] = fmaf(a, b.y, acc[4 * g + 1]);
            acc[4 * g + 2] = fmaf(a, b.z, acc[4 * g + 2]);
            acc[4 * g + 3] = fmaf(a, b.w, acc[4 * g + 3]);
        }
    }

    float4* Zn = g_Z4 + (size_t)n * NKER;
#pragma unroll
    for (int kk = 0; kk < NKER; kk++)
        Zn[kk] = make_float4(acc[3 * kk], acc[3 * kk + 1], acc[3 * kk + 2], 0.f);
    dout[n * 3 + 0] = acc[75];
    dout[n * 3 + 1] = acc[76];
    dout[n * 3 + 2] = acc[77];
}

// ---------------------------------------------------------------------------
// Edge pass 2: A4[dst] += sum_s basis1_s * Z[src, idx_s, :]  (one float4 atomic)
__global__ void k_edge2(const int* __restrict__ ei, const float* __restrict__ ps,
                        int E) {
    int e = blockIdx.x * blockDim.x + threadIdx.x;
    if (e >= E) return;
    int dst = ei[e];
    int src = ei[E + e];
    float2 p = reinterpret_cast<const float2*>(ps)[e];
    float b[4]; int id[4];
    spline4(p.x, p.y, b, id);
    const float4* Z = g_Z4 + (size_t)src * NKER;
    float a0 = 0.f, a1 = 0.f, a2 = 0.f;
#pragma unroll
    for (int s = 0; s < 4; s++) {
        float4 z = __ldg(Z + id[s]);
        a0 = fmaf(b[s], z.x, a0);
        a1 = fmaf(b[s], z.y, a1);
        a2 = fmaf(b[s], z.z, a2);
    }
    atomicAdd(g_A4 + dst, make_float4(a0, a1, a2, 0.f));
}

// ---------------------------------------------------------------------------
// Final: out[n] = root_term (already in dout) + inv[n] * A4[n]
__global__ void k_final(float* __restrict__ dout, int N) {
    int n = blockIdx.x * blockDim.x + threadIdx.x;
    if (n >= N) return;
    float4 a = g_A4[n];
    float inv = g_inv[n];
    dout[n * 3 + 0] += a.x * inv;
    dout[n * 3 + 1] += a.y * inv;
    dout[n * 3 + 2] += a.z * inv;
}

// ---------------------------------------------------------------------------
extern "C" void kernel_launch(void* const* d_in, const int* in_sizes, int n_in,
                              void* d_out, int out_size) {
    const float* x   = (const float*)d_in[0];
    const int*   ei  = (const int*)d_in[1];
    const float* ps  = (const float*)d_in[2];
    const float* ps1 = (const float*)d_in[3];
    const float* w   = (const float*)d_in[4];
    const float* rw  = (const float*)d_in[5];
    const float* w1  = (const float*)d_in[6];
    const float* rw1 = (const float*)d_in[7];
    float* dout = (float*)d_out;

    int N = in_sizes[0] / 6;
    int E = in_sizes[2] / 2;
    if (N > NMAX) N = NMAX;
    if (E > EMAX) E = EMAX;

    k_zero<<<2048, 256>>>(N);
    k_edge1<<<(E + 255) / 256, 256>>>(ei, ps, x, E);
    k_buildM<<<JD, 320>>>(w, rw, w1, rw1);

    size_t smemC = (size_t)(JD * MP) * sizeof(float);   // 49920 B
    cudaFuncSetAttribute(k_zgemm, cudaFuncAttributeMaxDynamicSharedMemorySize, (int)smemC);
    k_zgemm<<<(N + 127) / 128, 128, smemC>>>(x, dout, N);

    k_edge2<<<(E + 255) / 256, 256>>>(ei, ps1, E);
    k_final<<<(N + 255) / 256, 256>>>(dout, N);
}